// round 12
// baseline (speedup 1.0000x reference)
#include <cuda_runtime.h>
#include <cstdint>
#include <cstddef>

#define C_DIM   512
#define OUT_DIM 512
#define K_NEIGH 32
#define MAX_N   20000

// Scratch (allocation-free rule: __device__ global)
__device__ float g_agg[(size_t)MAX_N * C_DIM];

// ---------------------------------------------------------------------------
// Kernel 1: agg[n,c] = mean_k neigh[n,k,c]   (HBM-bound, streams 1.31 GB)
// ---------------------------------------------------------------------------
__global__ void mean_kernel(const float* __restrict__ neigh, int M) {
    int n = blockIdx.x;
    if (n >= M) return;
    int c4 = threadIdx.x;  // 0..127
    const float4* base = reinterpret_cast<const float4*>(neigh)
                       + (size_t)n * (K_NEIGH * C_DIM / 4) + c4;
    float4 s = make_float4(0.f, 0.f, 0.f, 0.f);
#pragma unroll
    for (int k = 0; k < K_NEIGH; ++k) {
        float4 v = base[(size_t)k * (C_DIM / 4)];
        s.x += v.x; s.y += v.y; s.z += v.z; s.w += v.w;
    }
    const float inv = 1.0f / (float)K_NEIGH;
    s.x *= inv; s.y *= inv; s.z *= inv; s.w *= inv;
    reinterpret_cast<float4*>(g_agg)[(size_t)n * (C_DIM / 4) + c4] = s;
}

// ---------------------------------------------------------------------------
// Kernel 2: tensor-core tf32 GEMM via mma.sync (m16n8k8).
//   out = [x | agg] @ [Wl | Wr]^T + (bl + br)
// CTA tile 128x256, BK=32, 3-stage cp.async ring, 8 warps (2x4), warp 64x64.
// Bigger warp tiles cut smem re-reads (crossbar was the R9/R10 bottleneck).
// Smem rows padded to 36 floats -> conflict-free fragment LDS.
// ---------------------------------------------------------------------------
#define BM 128
#define BN 256
#define BK 32
#define PAD_K 36                         // floats per smem row (144 B)
#define MAT_A_B  (BM * PAD_K * 4)        // 18432 B  (A tile)
#define MAT_B_B  (BN * PAD_K * 4)        // 36864 B  (B tile)
#define STAGE_B  (MAT_A_B + MAT_B_B)     // 55296 B per stage
#define OFF_BIAS (3 * STAGE_B)           // 165888
#define SMEM_TOTAL (OFF_BIAS + BN * 4)   // 166912

__device__ __forceinline__ uint32_t s2u(const void* p) {
    uint32_t a;
    asm("{ .reg .u64 t; cvta.to.shared.u64 t, %1; cvt.u32.u64 %0, t; }"
        : "=r"(a) : "l"(p));
    return a;
}

__device__ __forceinline__ void cp16(uint32_t dst, const void* src, int sz) {
    asm volatile("cp.async.cg.shared.global [%0], [%1], 16, %2;"
                 :: "r"(dst), "l"(src), "r"(sz) : "memory");
}

// load fp32 from smem, round-to-nearest-even into tf32 bit pattern
__device__ __forceinline__ uint32_t ld_tf32(const float* p) {
    uint32_t r;
    asm("cvt.rna.tf32.f32 %0, %1;" : "=r"(r) : "f"(*p));
    return r;
}

__global__ __launch_bounds__(256, 1)
void gemm_tc(const float* __restrict__ x,
             const float* __restrict__ Wl,
             const float* __restrict__ Wr,
             const float* __restrict__ bl,
             const float* __restrict__ br,
             float* __restrict__ out, int M) {
    extern __shared__ char smem[];
    const uint32_t sb = s2u(smem);
    float* smf = reinterpret_cast<float*>(smem);

    const int tid  = threadIdx.x;
    const int bm   = blockIdx.y * BM;
    const int bn   = blockIdx.x * BN;
    const int wid  = tid >> 5;
    const int lane = tid & 31;
    const int gid  = lane >> 2;        // 0..7
    const int tig  = lane & 3;         // 0..3
    const int wrow = wid >> 2;         // 0..1  -> 64-row slab (M)
    const int wcol = wid & 3;          // 0..3  -> 64-col slab (N)

    // bias into smem (BN=256 entries, all 256 threads)
    smf[OFF_BIAS / 4 + tid] = bl[bn + tid] + br[bn + tid];

    // ---- stage loader: chunk t in 0..31 ; t<16 -> (x,Wl) ; else (agg,Wr)
    auto load_stage = [&](int t) {
        const int half = t >> 4;
        const int k0   = (t & 15) * BK;
        const float* A = half ? g_agg : x;
        const float* W = half ? Wr : Wl;
        const uint32_t abase = sb + (t % 3) * STAGE_B;
        const uint32_t bbase = abase + MAT_A_B;
        // A tile: 128 rows x 8 chunks = 1024 chunks
#pragma unroll
        for (int i = 0; i < 4; i++) {
            const int c   = tid + i * 256;
            const int row = c >> 3;
            const int kc  = c & 7;
            const uint32_t so = row * (PAD_K * 4) + kc * 16;
            cp16(abase + so, A + (size_t)(bm + row) * C_DIM + k0 + kc * 4,
                 (bm + row < M) ? 16 : 0);
        }
        // B tile: 256 rows x 8 chunks = 2048 chunks
#pragma unroll
        for (int i = 0; i < 8; i++) {
            const int c   = tid + i * 256;
            const int row = c >> 3;
            const int kc  = c & 7;
            const uint32_t so = row * (PAD_K * 4) + kc * 16;
            cp16(bbase + so, W + (size_t)(bn + row) * C_DIM + k0 + kc * 4, 16);
        }
        asm volatile("cp.async.commit_group;" ::: "memory");
    };

    float acc[4][8][4];
#pragma unroll
    for (int i = 0; i < 4; i++)
#pragma unroll
        for (int j = 0; j < 8; j++)
#pragma unroll
            for (int v = 0; v < 4; v++) acc[i][j][v] = 0.f;

    load_stage(0);
    load_stage(1);

#pragma unroll 1
    for (int s = 0; s < 32; s++) {
        asm volatile("cp.async.wait_group 1;" ::: "memory");
        __syncthreads();                       // stage s visible; buf (s+2)%3 free
        if (s + 2 < 32) load_stage(s + 2);
        else asm volatile("cp.async.commit_group;" ::: "memory");

        const float* As = smf + ((s % 3) * STAGE_B) / 4;
        const float* Bs = As + MAT_A_B / 4;
        // per-thread fragment bases (conflict-free: bank = (4*gid+tig)%32)
        const float* ap = As + (wrow * 64 + gid) * PAD_K + tig;
        const float* bp = Bs + (wcol * 64 + gid) * PAD_K + tig;

#pragma unroll
        for (int kk = 0; kk < 4; kk++) {       // 4 x (K=8)
            const int k = kk * 8;
            uint32_t a[4][4], b[8][2];
#pragma unroll
            for (int mt = 0; mt < 4; mt++) {
                const float* p = ap + mt * 16 * PAD_K + k;
                a[mt][0] = ld_tf32(p);
                a[mt][1] = ld_tf32(p + 8 * PAD_K);
                a[mt][2] = ld_tf32(p + 4);
                a[mt][3] = ld_tf32(p + 8 * PAD_K + 4);
            }
#pragma unroll
            for (int nt = 0; nt < 8; nt++) {
                const float* p = bp + nt * 8 * PAD_K + k;
                b[nt][0] = ld_tf32(p);
                b[nt][1] = ld_tf32(p + 4);
            }
#pragma unroll
            for (int mt = 0; mt < 4; mt++)
#pragma unroll
                for (int nt = 0; nt < 8; nt++) {
                    asm volatile(
                        "mma.sync.aligned.m16n8k8.row.col.f32.tf32.tf32.f32 "
                        "{%0,%1,%2,%3}, {%4,%5,%6,%7}, {%8,%9}, {%0,%1,%2,%3};"
                        : "+f"(acc[mt][nt][0]), "+f"(acc[mt][nt][1]),
                          "+f"(acc[mt][nt][2]), "+f"(acc[mt][nt][3])
                        : "r"(a[mt][0]), "r"(a[mt][1]),
                          "r"(a[mt][2]), "r"(a[mt][3]),
                          "r"(b[nt][0]), "r"(b[nt][1]));
                }
        }
    }
    asm volatile("cp.async.wait_group 0;" ::: "memory");

    // ---- epilogue: bias + store (float2 per d-pair)
    const float* bias = smf + OFF_BIAS / 4;
#pragma unroll
    for (int mt = 0; mt < 4; mt++) {
        const int r0 = bm + wrow * 64 + mt * 16 + gid;
        const int r1 = r0 + 8;
#pragma unroll
        for (int nt = 0; nt < 8; nt++) {
            const int col  = wcol * 64 + nt * 8 + 2 * tig;
            const float b0 = bias[col], b1 = bias[col + 1];
            if (r0 < M) {
                float2 v = make_float2(acc[mt][nt][0] + b0, acc[mt][nt][1] + b1);
                *reinterpret_cast<float2*>(out + (size_t)r0 * OUT_DIM + bn + col) = v;
            }
            if (r1 < M) {
                float2 v = make_float2(acc[mt][nt][2] + b0, acc[mt][nt][3] + b1);
                *reinterpret_cast<float2*>(out + (size_t)r1 * OUT_DIM + bn + col) = v;
            }
        }
    }
}

extern "C" void kernel_launch(void* const* d_in, const int* in_sizes, int n_in,
                              void* d_out, int out_size) {
    const float* x     = (const float*)d_in[0];
    const float* neigh = (const float*)d_in[1];
    const float* Wl    = (const float*)d_in[2];
    const float* bl    = (const float*)d_in[3];
    const float* Wr    = (const float*)d_in[4];
    const float* br    = (const float*)d_in[5];
    float* out         = (float*)d_out;

    const int M = in_sizes[0] / C_DIM;   // 20000

    cudaFuncSetAttribute(gemm_tc, cudaFuncAttributeMaxDynamicSharedMemorySize,
                         SMEM_TOTAL);

    mean_kernel<<<M, 128>>>(neigh, M);

    dim3 grid(OUT_DIM / BN, (M + BM - 1) / BM);
    gemm_tc<<<grid, 256, SMEM_TOTAL>>>(x, Wl, Wr, bl, br, out, M);
}

// round 14
// speedup vs baseline: 1.0915x; 1.0915x over previous
#include <cuda_runtime.h>
#include <cstdint>
#include <cstddef>

#define C_DIM   512
#define OUT_DIM 512
#define K_NEIGH 32
#define MAX_N   20000

// Scratch (allocation-free rule: __device__ globals)
__device__ float g_agg[(size_t)MAX_N * C_DIM];   // tf32-rounded neighbor mean
__device__ float g_xr [(size_t)MAX_N * C_DIM];   // tf32-rounded x
__device__ float g_wl [(size_t)OUT_DIM * C_DIM]; // tf32-rounded W_l
__device__ float g_wr [(size_t)OUT_DIM * C_DIM]; // tf32-rounded W_r

__device__ __forceinline__ float f2tf32(float a) {
    float r; asm("cvt.rna.tf32.f32 %0, %1;" : "=f"(r) : "f"(a)); return r;
}

// ---------------------------------------------------------------------------
// Kernel 1: agg[n,c] = tf32_round( mean_k neigh[n,k,c] )  (HBM-bound, 1.31GB)
// ---------------------------------------------------------------------------
__global__ void mean_kernel(const float* __restrict__ neigh, int M) {
    int n = blockIdx.x;
    if (n >= M) return;
    int c4 = threadIdx.x;  // 0..127
    const float4* base = reinterpret_cast<const float4*>(neigh)
                       + (size_t)n * (K_NEIGH * C_DIM / 4) + c4;
    float4 s = make_float4(0.f, 0.f, 0.f, 0.f);
#pragma unroll
    for (int k = 0; k < K_NEIGH; ++k) {
        float4 v = base[(size_t)k * (C_DIM / 4)];
        s.x += v.x; s.y += v.y; s.z += v.z; s.w += v.w;
    }
    const float inv = 1.0f / (float)K_NEIGH;
    s.x = f2tf32(s.x * inv); s.y = f2tf32(s.y * inv);
    s.z = f2tf32(s.z * inv); s.w = f2tf32(s.w * inv);
    reinterpret_cast<float4*>(g_agg)[(size_t)n * (C_DIM / 4) + c4] = s;
}

// tf32-RNA pre-round of x (so the GEMM can consume raw bits, no in-loop CVT)
__global__ void round_x_kernel(const float* __restrict__ x, int n4) {
    int i = blockIdx.x * blockDim.x + threadIdx.x;
    int stride = gridDim.x * blockDim.x;
    for (; i < n4; i += stride) {
        float4 v = reinterpret_cast<const float4*>(x)[i];
        v.x = f2tf32(v.x); v.y = f2tf32(v.y);
        v.z = f2tf32(v.z); v.w = f2tf32(v.w);
        reinterpret_cast<float4*>(g_xr)[i] = v;
    }
}

__global__ void round_w_kernel(const float* __restrict__ Wl,
                               const float* __restrict__ Wr) {
    int i = blockIdx.x * blockDim.x + threadIdx.x;  // 0..65535
    float4 a = reinterpret_cast<const float4*>(Wl)[i];
    a.x = f2tf32(a.x); a.y = f2tf32(a.y); a.z = f2tf32(a.z); a.w = f2tf32(a.w);
    reinterpret_cast<float4*>(g_wl)[i] = a;
    float4 b = reinterpret_cast<const float4*>(Wr)[i];
    b.x = f2tf32(b.x); b.y = f2tf32(b.y); b.z = f2tf32(b.z); b.w = f2tf32(b.w);
    reinterpret_cast<float4*>(g_wr)[i] = b;
}

// ---------------------------------------------------------------------------
// Kernel 2: tf32 GEMM via mma.sync (m16n8k8) with ldmatrix fragment loads.
//   out = [xr | agg] @ [Wl | Wr]^T + (bl + br)
// CTA tile 128x128, BK=32, 3-stage cp.async ring, 8 warps (2x4), warp 64x32.
// Inputs pre-rounded to tf32 -> fragments are raw bits via ldmatrix.b16
// (16B row = 4 tf32; x4 = one m16k8 A-frag, x2 = one n8k8 B-frag).
// 2 CTAs/SM resident (smem 111KB, ~110 regs).
// ---------------------------------------------------------------------------
#define BM 128
#define BN 128
#define BK 32
#define PAD_K 36                       // floats per smem row (144 B)
#define MAT_B   (BM * PAD_K * 4)       // 18432 B per matrix
#define STAGE_B (2 * MAT_B)            // 36864 B per stage
#define OFF_BIAS (3 * STAGE_B)         // 110592
#define SMEM_TOTAL (OFF_BIAS + BN * 4) // 111104

__device__ __forceinline__ uint32_t s2u(const void* p) {
    uint32_t a;
    asm("{ .reg .u64 t; cvta.to.shared.u64 t, %1; cvt.u32.u64 %0, t; }"
        : "=r"(a) : "l"(p));
    return a;
}

__device__ __forceinline__ void cp16(uint32_t dst, const void* src, int sz) {
    asm volatile("cp.async.cg.shared.global [%0], [%1], 16, %2;"
                 :: "r"(dst), "l"(src), "r"(sz) : "memory");
}

__device__ __forceinline__ void ldsm_x4(uint32_t addr, uint32_t* r) {
    asm volatile("ldmatrix.sync.aligned.m8n8.x4.shared.b16 {%0,%1,%2,%3}, [%4];"
                 : "=r"(r[0]), "=r"(r[1]), "=r"(r[2]), "=r"(r[3]) : "r"(addr));
}

__device__ __forceinline__ void ldsm_x2(uint32_t addr, uint32_t* r) {
    asm volatile("ldmatrix.sync.aligned.m8n8.x2.shared.b16 {%0,%1}, [%2];"
                 : "=r"(r[0]), "=r"(r[1]) : "r"(addr));
}

__global__ __launch_bounds__(256, 2)
void gemm_tc(const float* __restrict__ bl,
             const float* __restrict__ br,
             float* __restrict__ out, int M) {
    extern __shared__ char smem[];
    const uint32_t sb = s2u(smem);
    float* smf = reinterpret_cast<float*>(smem);

    const int tid  = threadIdx.x;
    const int bm   = blockIdx.y * BM;
    const int bn   = blockIdx.x * BN;
    const int wid  = tid >> 5;
    const int lane = tid & 31;
    const int gid  = lane >> 2;        // 0..7
    const int tig  = lane & 3;         // 0..3
    const int wrow = wid >> 2;         // 0..1  -> 64-row slab (M)
    const int wcol = wid & 3;          // 0..3  -> 32-col slab (N)

    // bias into smem (BN=128 entries, first 128 threads only)
    if (tid < BN)
        smf[OFF_BIAS / 4 + tid] = bl[bn + tid] + br[bn + tid];

    // ldmatrix per-lane base offsets (bytes, within a stage's A / B matrix)
    // A (x4): lanes 0-7 rows 0-7 col+0 | 8-15 rows 8-15 col+0
    //         | 16-23 rows 0-7 col+4 | 24-31 rows 8-15 col+4
    const uint32_t aoff =
        (uint32_t)((wrow * 64 + (lane & 15)) * PAD_K + (lane >> 4) * 4) * 4u;
    // B (x2): lanes 0-7 rows 0-7 col+0 | 8-15 rows 0-7 col+4 (rest ignored)
    const uint32_t boff =
        (uint32_t)((wcol * 32 + (lane & 7)) * PAD_K + ((lane >> 3) & 1) * 4) * 4u;

    // ---- stage loader: chunk t in 0..31 ; t<16 -> (xr,Wl) ; else (agg,Wr)
    auto load_stage = [&](int t) {
        const int half = t >> 4;
        const int k0   = (t & 15) * BK;
        const float* A = half ? g_agg : g_xr;
        const float* W = half ? g_wr : g_wl;
        const uint32_t abase = sb + (t % 3) * STAGE_B;
        const uint32_t bbase = abase + MAT_B;
#pragma unroll
        for (int i = 0; i < 4; i++) {
            const int c   = tid + i * 256;   // 0..1023
            const int row = c >> 3;          // 0..127
            const int kc  = c & 7;           // 16B chunk within 32-float row
            const uint32_t so = row * (PAD_K * 4) + kc * 16;
            cp16(abase + so, A + (size_t)(bm + row) * C_DIM + k0 + kc * 4,
                 (bm + row < M) ? 16 : 0);
            cp16(bbase + so, W + (size_t)(bn + row) * C_DIM + k0 + kc * 4, 16);
        }
        asm volatile("cp.async.commit_group;" ::: "memory");
    };

    float acc[4][4][4];
#pragma unroll
    for (int i = 0; i < 4; i++)
#pragma unroll
        for (int j = 0; j < 4; j++)
#pragma unroll
            for (int v = 0; v < 4; v++) acc[i][j][v] = 0.f;

    load_stage(0);
    load_stage(1);

#pragma unroll 1
    for (int s = 0; s < 32; s++) {
        asm volatile("cp.async.wait_group 1;" ::: "memory");
        __syncthreads();                       // stage s visible; buf (s+2)%3 free
        if (s + 2 < 32) load_stage(s + 2);
        else asm volatile("cp.async.commit_group;" ::: "memory");

        const uint32_t abase = sb + (s % 3) * STAGE_B + aoff;
        const uint32_t bbase = sb + (s % 3) * STAGE_B + MAT_B + boff;

#pragma unroll
        for (int kk = 0; kk < 4; kk++) {       // 4 x (K=8)
            uint32_t a[4][4], b[4][2];
#pragma unroll
            for (int mt = 0; mt < 4; mt++)
                ldsm_x4(abase + (mt * 16 * PAD_K + kk * 8) * 4, a[mt]);
#pragma unroll
            for (int nt = 0; nt < 4; nt++)
                ldsm_x2(bbase + (nt * 8 * PAD_K + kk * 8) * 4, b[nt]);
#pragma unroll
            for (int mt = 0; mt < 4; mt++)
#pragma unroll
                for (int nt = 0; nt < 4; nt++) {
                    asm volatile(
                        "mma.sync.aligned.m16n8k8.row.col.f32.tf32.tf32.f32 "
                        "{%0,%1,%2,%3}, {%4,%5,%6,%7}, {%8,%9}, {%0,%1,%2,%3};"
                        : "+f"(acc[mt][nt][0]), "+f"(acc[mt][nt][1]),
                          "+f"(acc[mt][nt][2]), "+f"(acc[mt][nt][3])
                        : "r"(a[mt][0]), "r"(a[mt][1]),
                          "r"(a[mt][2]), "r"(a[mt][3]),
                          "r"(b[nt][0]), "r"(b[nt][1]));
                }
        }
    }
    asm volatile("cp.async.wait_group 0;" ::: "memory");

    // ---- epilogue: bias + store (float2 per d-pair)
    const float* bias = smf + OFF_BIAS / 4;
#pragma unroll
    for (int mt = 0; mt < 4; mt++) {
        const int r0 = bm + wrow * 64 + mt * 16 + gid;
        const int r1 = r0 + 8;
#pragma unroll
        for (int nt = 0; nt < 4; nt++) {
            const int col  = wcol * 32 + nt * 8 + 2 * tig;
            const float b0 = bias[col], b1 = bias[col + 1];
            if (r0 < M) {
                float2 v = make_float2(acc[mt][nt][0] + b0, acc[mt][nt][1] + b1);
                *reinterpret_cast<float2*>(out + (size_t)r0 * OUT_DIM + bn + col) = v;
            }
            if (r1 < M) {
                float2 v = make_float2(acc[mt][nt][2] + b0, acc[mt][nt][3] + b1);
                *reinterpret_cast<float2*>(out + (size_t)r1 * OUT_DIM + bn + col) = v;
            }
        }
    }
}

extern "C" void kernel_launch(void* const* d_in, const int* in_sizes, int n_in,
                              void* d_out, int out_size) {
    const float* x     = (const float*)d_in[0];
    const float* neigh = (const float*)d_in[1];
    const float* Wl    = (const float*)d_in[2];
    const float* bl    = (const float*)d_in[3];
    const float* Wr    = (const float*)d_in[4];
    const float* br    = (const float*)d_in[5];
    float* out         = (float*)d_out;

    const int M = in_sizes[0] / C_DIM;   // 20000

    cudaFuncSetAttribute(gemm_tc, cudaFuncAttributeMaxDynamicSharedMemorySize,
                         SMEM_TOTAL);

    mean_kernel<<<M, 128>>>(neigh, M);
    round_x_kernel<<<2048, 256>>>(x, M * C_DIM / 4);
    round_w_kernel<<<OUT_DIM * C_DIM / 4 / 256, 256>>>(Wl, Wr);

    dim3 grid(OUT_DIM / BN, (M + BM - 1) / BM);
    gemm_tc<<<grid, 256, SMEM_TOTAL>>>(bl, br, out, M);
}